// round 11
// baseline (speedup 1.0000x reference)
#include <cuda_runtime.h>
#include <cstdint>

#define BB 64
#define TT 4096
#define CC 51
#define DD 64
#define NTHREADS 128
#define TOKS 64               // tokens per block
#define LN_EPS 1e-5f

typedef unsigned long long ull;

// Packed fp32x2 FMA (Blackwell FFMA2 — PTX-only)
#define FMA2(d, a, b, c) \
    asm("fma.rn.f32x2 %0, %1, %2, %3;" : "=l"(d) : "l"(a), "l"(b), "l"(c))

static __device__ __forceinline__ float lo32(ull v) { return __uint_as_float((unsigned)v); }
static __device__ __forceinline__ float hi32(ull v) { return __uint_as_float((unsigned)(v >> 32)); }
static __device__ __forceinline__ ull pack2(float x, float y) {
    return (ull)__float_as_uint(x) | ((ull)__float_as_uint(y) << 32);
}
static __device__ __forceinline__ ull dup2(float x) { return pack2(x, x); }

// ---------------------------------------------------------------------------
// Globals written by precompute kernel
// ---------------------------------------------------------------------------
__device__ int    g_mask_dtype;        // 1=int32 {0,1}, 2=float32 {0,1.0f}, 0=uint8
__device__ float  g_bias[BB * DD];     // per batch: sum of Wm over sensor-masked c
__device__ float2 g_cvec[BB * 32];     // per batch, lane: LN(sum_all Wm) const row

static __device__ __forceinline__ int mask_val(const void* p, long i, int dt)
{
    if (dt == 1) return ((const int*)p)[i] != 0;
    if (dt == 2) return ((const float*)p)[i] != 0.0f;
    return ((const unsigned char*)p)[i] != 0;
}

// ---------------------------------------------------------------------------
// Per-batch precompute (grid=64, block=32). Self-detects mask dtype from the
// first 1024 words of time_mask (Bernoulli(0.3): classification unambiguous).
// ---------------------------------------------------------------------------
extern "C" __global__ void precompute_batch_kernel(const float* __restrict__ Wm,
                                                   const void* __restrict__ smask,
                                                   const float* __restrict__ gamma,
                                                   const float* __restrict__ beta,
                                                   const unsigned* __restrict__ tmw)
{
    const int b = blockIdx.x, lane = threadIdx.x;

    int ok_i = 1, ok_f = 1;
#pragma unroll
    for (int k = 0; k < 32; ++k) {
        unsigned w = tmw[lane + 32 * k];
        if (w > 1u)                      ok_i = 0;
        if (w != 0u && w != 0x3f800000u) ok_f = 0;
    }
    ok_i = __all_sync(0xffffffffu, ok_i);
    ok_f = __all_sync(0xffffffffu, ok_f);
    const int dt = ok_i ? 1 : (ok_f ? 2 : 0);
    if (b == 0 && lane == 0) g_mask_dtype = dt;

    float2 ws = make_float2(0.f, 0.f), bs = make_float2(0.f, 0.f);
#pragma unroll
    for (int c = 0; c < CC; ++c) {
        float2 wm = *(const float2*)(Wm + c * DD + 2 * lane);
        ws.x += wm.x; ws.y += wm.y;
        if (mask_val(smask, (long)b * CC + c, dt)) { bs.x += wm.x; bs.y += wm.y; }
    }
    float2 g2 = *(const float2*)(gamma + 2 * lane);
    float2 b2 = *(const float2*)(beta  + 2 * lane);
    float s = ws.x + ws.y, q = ws.x * ws.x + ws.y * ws.y;
#pragma unroll
    for (int o = 16; o > 0; o >>= 1) {
        s += __shfl_xor_sync(0xffffffffu, s, o);
        q += __shfl_xor_sync(0xffffffffu, q, o);
    }
    float mu = s * (1.f / 64.f);
    float r  = rsqrtf(fmaf(-mu, mu, q * (1.f / 64.f)) + LN_EPS);
    float2 cv;
    cv.x = fmaf((ws.x - mu) * r, g2.x, b2.x);
    cv.y = fmaf((ws.y - mu) * r, g2.y, b2.y);
    g_bias[b * DD + 2 * lane]     = bs.x;
    g_bias[b * DD + 2 * lane + 1] = bs.y;
    g_cvec[b * 32 + lane]         = cv;
}

// ---------------------------------------------------------------------------
// Main kernel SMEM layout (bytes):
//   [0)      ull xs[64][52]          duplicated (x,x), token-compacted = 26624
//   [26624)  ulonglong2 Wsh2[26][32] W col-pairs per-lane d            = 13312
//   [39936)  int tokmap[64]
//   [40192)  int slotmap[64]
//   [40448)  int wcnt[4]
//   [40464)  uchar sm_sh[64]
// ---------------------------------------------------------------------------
#define SM_XS    0
#define SM_WD    26624
#define SM_TOK   39936
#define SM_SLOT  40192
#define SM_WCNT  40448
#define SM_SMSH  40464
#define SM_TOTAL 40528

extern "C" __global__ void __launch_bounds__(NTHREADS, 5)
fused_proj_ln_kernel(const float* __restrict__ x,
                     const float* __restrict__ W,
                     const float* __restrict__ gamma,
                     const float* __restrict__ beta,
                     const void* __restrict__ time_mask,
                     const void* __restrict__ sensor_mask,
                     float* __restrict__ out)
{
    extern __shared__ char smem[];
    ull*           xs      = (ull*)(smem + SM_XS);
    ulonglong2*    Wsh2    = (ulonglong2*)(smem + SM_WD);
    int*           tokmap  = (int*)(smem + SM_TOK);
    int*           slotmap = (int*)(smem + SM_SLOT);
    int*           wcnt    = (int*)(smem + SM_WCNT);
    unsigned char* sm_sh   = (unsigned char*)(smem + SM_SMSH);

    const int tid  = threadIdx.x;
    const int lane = tid & 31;
    const int wid  = tid >> 5;

    const int  b    = blockIdx.x >> 6;            // 64 tiles per batch
    const int  tb   = (blockIdx.x & 63) * TOKS;
    const long tok0 = (long)b * TT + tb;
    const int  dt   = g_mask_dtype;

    // ---- phase 1: masks, ballots, pad init ----
    if (tid < CC) sm_sh[tid] = (unsigned char)mask_val(sensor_mask, (long)b * CC + tid, dt);
    if (tid < TOKS) { tokmap[tid] = 0; xs[tid * 52 + 51] = 0ull; }

    // each warp owns 16 tokens: token = wid*16 + lane  (lane < 16)
    const int myTok = wid * 16 + lane;
    int un = 0;
    if (lane < 16) un = !mask_val(time_mask, tok0 + myTok, dt);
    const unsigned um16 = __ballot_sync(0xffffffffu, un);
    if (lane == 0) wcnt[wid] = __popc(um16);
    __syncthreads();                                         // #1

    // ---- phase 2: compaction maps + x LDG batch + W staging (overlapped) ----
    int woff = 0;
#pragma unroll
    for (int w = 0; w < 4; ++w) woff += (w < wid) ? wcnt[w] : 0;
    const int nslots  = wcnt[0] + wcnt[1] + wcnt[2] + wcnt[3];
    const int ngroups = (nslots + 7) >> 3;
    if (lane < 16) {
        const int myslot = woff + __popc(um16 & ((1u << lane) - 1u));
        slotmap[myTok] = un ? myslot : -1;
        if (un) tokmap[myslot] = myTok;
    }

    // x LDG batch: 816 float4 per tile (64*51 floats), MLP-7
    const float4* xg4 = (const float4*)(x + tok0 * CC);
    float4 vv[7];
#pragma unroll
    for (int k = 0; k < 6; ++k) vv[k] = xg4[tid + 128 * k];
    const bool tail = tid < 48;
    if (tail) vv[6] = xg4[768 + tid];

    // W -> SMEM: interleaved column-pair layout, masked columns zeroed
    for (int j = wid; j < 26; j += 4) {
        int c0 = 2 * j, c1 = 2 * j + 1;
        ull w0 = sm_sh[c0] ? 0ull : *(const ull*)(W + c0 * DD + 2 * lane);
        ull w1 = (c1 < CC && !sm_sh[c1]) ? *(const ull*)(W + c1 * DD + 2 * lane) : 0ull;
        ulonglong2 t; t.x = w0; t.y = w1;
        Wsh2[j * 32 + lane] = t;
    }
    __syncthreads();                                         // #2 (slotmap ready)

    // ---- phase 3: scatter x into compacted duplicated rows ----
    {
        int idx = 4 * tid;
        int tok = idx / CC;
        int col = idx - tok * CC;
#pragma unroll
        for (int k = 0; k < 7; ++k) {
            if (k < 6 || tail) {
                float4 v = vv[k];
                int t = tok, c = col;
                int s = slotmap[t];
                if (s >= 0) xs[s * 52 + c] = dup2(v.x);
                if (++c == CC) { c = 0; s = slotmap[++t]; }
                if (s >= 0) xs[s * 52 + c] = dup2(v.y);
                if (++c == CC) { c = 0; s = slotmap[++t]; }
                if (s >= 0) xs[s * 52 + c] = dup2(v.z);
                if (++c == CC) { c = 0; s = slotmap[++t]; }
                if (s >= 0) xs[s * 52 + c] = dup2(v.w);
            }
            tok += 10; col += 2;                             // advance by 512 floats
            if (col >= CC) { col -= CC; ++tok; }
        }
    }

    // ---- per-lane constants + masked-token constant stores ----
    const float2 bb   = *(const float2*)(g_bias + b * DD + 2 * lane);
    const ull    bll  = pack2(bb.x, bb.y);
    const float2 cvec = g_cvec[b * 32 + lane];
    const float2 g2   = *(const float2*)(gamma + 2 * lane);
    const float2 b2   = *(const float2*)(beta  + 2 * lane);
    float2* out2 = (float2*)out;
    {
        unsigned mm = ~um16 & 0xffffu;
        float2* ob = out2 + (tok0 + wid * 16) * 32 + lane;
#pragma unroll
        for (int r = 0; r < 16; ++r)
            if ((mm >> r) & 1u) ob[r * 32] = cvec;
    }
    __syncthreads();                                         // #3 (xs ready)

    // ---- phase 4: compute — groups of 8 compacted slots, round-robin ----
    for (int g = wid; g < ngroups; g += 4) {
        const int base = g * 8;
        const int nv   = nslots - base;        // >=1; >=8 except last group

        const ulonglong2* xb = (const ulonglong2*)(xs + base * 52);
        ull a0 = bll, a1 = bll, a2 = bll, a3 = bll;
        ull a4 = bll, a5 = bll, a6 = bll, a7 = bll;

#pragma unroll
        for (int gi = 0; gi < 13; ++gi) {
            ulonglong2 wA = Wsh2[(2 * gi) * 32 + lane];      // cols 4gi, 4gi+1
            ulonglong2 wB = Wsh2[(2 * gi + 1) * 32 + lane];  // cols 4gi+2, 4gi+3
            {
                ulonglong2 u = xb[0 * 26 + 2 * gi], v = xb[0 * 26 + 2 * gi + 1];
                FMA2(a0, u.x, wA.x, a0); FMA2(a0, u.y, wA.y, a0);
                FMA2(a0, v.x, wB.x, a0); FMA2(a0, v.y, wB.y, a0);
            }
            {
                ulonglong2 u = xb[1 * 26 + 2 * gi], v = xb[1 * 26 + 2 * gi + 1];
                FMA2(a1, u.x, wA.x, a1); FMA2(a1, u.y, wA.y, a1);
                FMA2(a1, v.x, wB.x, a1); FMA2(a1, v.y, wB.y, a1);
            }
            {
                ulonglong2 u = xb[2 * 26 + 2 * gi], v = xb[2 * 26 + 2 * gi + 1];
                FMA2(a2, u.x, wA.x, a2); FMA2(a2, u.y, wA.y, a2);
                FMA2(a2, v.x, wB.x, a2); FMA2(a2, v.y, wB.y, a2);
            }
            {
                ulonglong2 u = xb[3 * 26 + 2 * gi], v = xb[3 * 26 + 2 * gi + 1];
                FMA2(a3, u.x, wA.x, a3); FMA2(a3, u.y, wA.y, a3);
                FMA2(a3, v.x, wB.x, a3); FMA2(a3, v.y, wB.y, a3);
            }
            {
                ulonglong2 u = xb[4 * 26 + 2 * gi], v = xb[4 * 26 + 2 * gi + 1];
                FMA2(a4, u.x, wA.x, a4); FMA2(a4, u.y, wA.y, a4);
                FMA2(a4, v.x, wB.x, a4); FMA2(a4, v.y, wB.y, a4);
            }
            {
                ulonglong2 u = xb[5 * 26 + 2 * gi], v = xb[5 * 26 + 2 * gi + 1];
                FMA2(a5, u.x, wA.x, a5); FMA2(a5, u.y, wA.y, a5);
                FMA2(a5, v.x, wB.x, a5); FMA2(a5, v.y, wB.y, a5);
            }
            {
                ulonglong2 u = xb[6 * 26 + 2 * gi], v = xb[6 * 26 + 2 * gi + 1];
                FMA2(a6, u.x, wA.x, a6); FMA2(a6, u.y, wA.y, a6);
                FMA2(a6, v.x, wB.x, a6); FMA2(a6, v.y, wB.y, a6);
            }
            {
                ulonglong2 u = xb[7 * 26 + 2 * gi], v = xb[7 * 26 + 2 * gi + 1];
                FMA2(a7, u.x, wA.x, a7); FMA2(a7, u.y, wA.y, a7);
                FMA2(a7, v.x, wB.x, a7); FMA2(a7, v.y, wB.y, a7);
            }
        }

        // ---- fused LN for 8 chains + guarded stores ----
        ull aa[8] = {a0, a1, a2, a3, a4, a5, a6, a7};
        float xv[8], yv[8], sv[8], qv[8];
#pragma unroll
        for (int k = 0; k < 8; ++k) {
            xv[k] = lo32(aa[k]); yv[k] = hi32(aa[k]);
            sv[k] = xv[k] + yv[k];
            qv[k] = xv[k] * xv[k] + yv[k] * yv[k];
        }
#pragma unroll
        for (int o = 16; o > 0; o >>= 1) {
#pragma unroll
            for (int k = 0; k < 8; ++k) {
                sv[k] += __shfl_xor_sync(0xffffffffu, sv[k], o);
                qv[k] += __shfl_xor_sync(0xffffffffu, qv[k], o);
            }
        }
#pragma unroll
        for (int k = 0; k < 8; ++k) {
            float mu = sv[k] * (1.f / 64.f);
            float r  = rsqrtf(fmaf(-mu, mu, qv[k] * (1.f / 64.f)) + LN_EPS);
            if (k < nv) {
                float2 o2;
                o2.x = fmaf((xv[k] - mu) * r, g2.x, b2.x);
                o2.y = fmaf((yv[k] - mu) * r, g2.y, b2.y);
                out2[(tok0 + tokmap[base + k]) * 32 + lane] = o2;
            }
        }
    }
}

extern "C" void kernel_launch(void* const* d_in, const int* in_sizes, int n_in,
                              void* d_out, int out_size)
{
    const float* x     = (const float*)d_in[0];
    const float* W     = (const float*)d_in[1];
    const float* Wm    = (const float*)d_in[2];
    const float* gamma = (const float*)d_in[3];
    const float* beta  = (const float*)d_in[4];
    const void*  tmask = d_in[5];
    const void*  smask = d_in[6];

    (void)in_sizes; (void)n_in; (void)out_size;

    cudaFuncSetAttribute(fused_proj_ln_kernel,
                         cudaFuncAttributeMaxDynamicSharedMemorySize, SM_TOTAL);

    precompute_batch_kernel<<<BB, 32>>>(Wm, smask, gamma, beta,
                                        (const unsigned*)tmask);

    const int nblocks = BB * (TT / TOKS);   // 4096
    fused_proj_ln_kernel<<<nblocks, NTHREADS, SM_TOTAL>>>(
        x, W, gamma, beta, tmask, smask, (float*)d_out);
}

// round 12
// speedup vs baseline: 1.3283x; 1.3283x over previous
#include <cuda_runtime.h>
#include <cstdint>

#define BB 64
#define TT 4096
#define CC 51
#define DD 64
#define NTHREADS 128
#define LN_EPS 1e-5f

typedef unsigned long long ull;

// Packed fp32x2 FMA (Blackwell FFMA2 — PTX-only)
#define FMA2(d, a, b, c) \
    asm("fma.rn.f32x2 %0, %1, %2, %3;" : "=l"(d) : "l"(a), "l"(b), "l"(c))

static __device__ __forceinline__ float lo32(ull v) { return __uint_as_float((unsigned)v); }
static __device__ __forceinline__ float hi32(ull v) { return __uint_as_float((unsigned)(v >> 32)); }
static __device__ __forceinline__ ull pack2(float x, float y) {
    return (ull)__float_as_uint(x) | ((ull)__float_as_uint(y) << 32);
}
static __device__ __forceinline__ ull dup2(float x) { return pack2(x, x); }

// ---------------------------------------------------------------------------
// Globals written by precompute kernel
// ---------------------------------------------------------------------------
__device__ int    g_mask_dtype;        // 1=int32 {0,1}, 2=float32 {0,1.0f}, 0=uint8
__device__ float  g_bias[BB * DD];     // per batch: sum of Wm over sensor-masked c
__device__ float2 g_cvec[BB * 32];     // per batch, lane: LN(sum_all Wm) const row

static __device__ __forceinline__ int mask_val(const void* p, long i, int dt)
{
    if (dt == 1) return ((const int*)p)[i] != 0;
    if (dt == 2) return ((const float*)p)[i] != 0.0f;
    return ((const unsigned char*)p)[i] != 0;
}

// ---------------------------------------------------------------------------
// Per-batch precompute (grid=64, block=32). Self-detects mask dtype from the
// first 1024 words of time_mask (Bernoulli(0.3): classification unambiguous).
// ---------------------------------------------------------------------------
extern "C" __global__ void precompute_batch_kernel(const float* __restrict__ Wm,
                                                   const void* __restrict__ smask,
                                                   const float* __restrict__ gamma,
                                                   const float* __restrict__ beta,
                                                   const unsigned* __restrict__ tmw)
{
    const int b = blockIdx.x, lane = threadIdx.x;

    int ok_i = 1, ok_f = 1;
#pragma unroll
    for (int k = 0; k < 32; ++k) {
        unsigned w = tmw[lane + 32 * k];
        if (w > 1u)                      ok_i = 0;
        if (w != 0u && w != 0x3f800000u) ok_f = 0;
    }
    ok_i = __all_sync(0xffffffffu, ok_i);
    ok_f = __all_sync(0xffffffffu, ok_f);
    const int dt = ok_i ? 1 : (ok_f ? 2 : 0);
    if (b == 0 && lane == 0) g_mask_dtype = dt;

    float2 ws = make_float2(0.f, 0.f), bs = make_float2(0.f, 0.f);
#pragma unroll
    for (int c = 0; c < CC; ++c) {
        float2 wm = *(const float2*)(Wm + c * DD + 2 * lane);
        ws.x += wm.x; ws.y += wm.y;
        if (mask_val(smask, (long)b * CC + c, dt)) { bs.x += wm.x; bs.y += wm.y; }
    }
    float2 g2 = *(const float2*)(gamma + 2 * lane);
    float2 b2 = *(const float2*)(beta  + 2 * lane);
    float s = ws.x + ws.y, q = ws.x * ws.x + ws.y * ws.y;
#pragma unroll
    for (int o = 16; o > 0; o >>= 1) {
        s += __shfl_xor_sync(0xffffffffu, s, o);
        q += __shfl_xor_sync(0xffffffffu, q, o);
    }
    float mu = s * (1.f / 64.f);
    float r  = rsqrtf(fmaf(-mu, mu, q * (1.f / 64.f)) + LN_EPS);
    float2 cv;
    cv.x = fmaf((ws.x - mu) * r, g2.x, b2.x);
    cv.y = fmaf((ws.y - mu) * r, g2.y, b2.y);
    g_bias[b * DD + 2 * lane]     = bs.x;
    g_bias[b * DD + 2 * lane + 1] = bs.y;
    g_cvec[b * 32 + lane]         = cv;
}

// ---------------------------------------------------------------------------
// Main kernel SMEM layout (bytes):
//   [0)      ull xs[128][52]          duplicated (x,x), block-compacted = 53248
//   [53248)  ulonglong2 Wsh2[26][32]  W col-pairs per-lane d            = 13312
//   [66560)  int tokmap[128]
//   [67072)  int slotmap[128]
//   [67584)  int wcnt[4]
//   [67600)  uchar sm_sh[64]
// ---------------------------------------------------------------------------
#define SM_XS    0
#define SM_WD    53248
#define SM_TOK   66560
#define SM_SLOT  67072
#define SM_WCNT  67584
#define SM_SMSH  67600
#define SM_TOTAL 67664

extern "C" __global__ void __launch_bounds__(NTHREADS, 3)
fused_proj_ln_kernel(const float* __restrict__ x,
                     const float* __restrict__ W,
                     const float* __restrict__ gamma,
                     const float* __restrict__ beta,
                     const void* __restrict__ time_mask,
                     const void* __restrict__ sensor_mask,
                     float* __restrict__ out)
{
    extern __shared__ char smem[];
    ull*           xs      = (ull*)(smem + SM_XS);
    ulonglong2*    Wsh2    = (ulonglong2*)(smem + SM_WD);
    int*           tokmap  = (int*)(smem + SM_TOK);
    int*           slotmap = (int*)(smem + SM_SLOT);
    int*           wcnt    = (int*)(smem + SM_WCNT);
    unsigned char* sm_sh   = (unsigned char*)(smem + SM_SMSH);

    const int tid  = threadIdx.x;
    const int lane = tid & 31;
    const int wid  = tid >> 5;

    const int  b    = blockIdx.x >> 5;            // 32 tiles per batch
    const int  tb   = (blockIdx.x & 31) * 128;
    const long tok0 = (long)b * TT + tb;
    const int  dt   = g_mask_dtype;

    // ---- phase 1: masks, ballot, pad init ----
    if (tid < CC) sm_sh[tid] = (unsigned char)mask_val(sensor_mask, (long)b * CC + tid, dt);
    tokmap[tid] = 0;
    xs[tid * 52 + 51] = 0ull;                     // pad column (valid slots only matter)

    // each warp owns 32 consecutive tokens
    const int myTok = wid * 32 + lane;
    const int un    = !mask_val(time_mask, tok0 + myTok, dt);
    const unsigned um = __ballot_sync(0xffffffffu, un);
    if (lane == 0) wcnt[wid] = __popc(um);
    __syncthreads();                                         // #1

    // ---- phase 2: compaction maps + x LDG batch + W staging (overlapped) ----
    int woff = 0;
#pragma unroll
    for (int w = 0; w < 4; ++w) woff += (w < wid) ? wcnt[w] : 0;
    const int nslots  = wcnt[0] + wcnt[1] + wcnt[2] + wcnt[3];
    const int ngroups = (nslots + 15) >> 4;
    {
        const int myslot = woff + __popc(um & ((1u << lane) - 1u));
        slotmap[myTok] = un ? myslot : -1;
        if (un) tokmap[myslot] = myTok;
    }

    // x LDG batch: 1632 float4 per tile (128*51 floats), MLP-13
    const float4* xg4 = (const float4*)(x + tok0 * CC);
    float4 vv[13];
#pragma unroll
    for (int k = 0; k < 12; ++k) vv[k] = xg4[tid + 128 * k];
    const bool tail = tid < 96;                              // 1632 - 1536
    if (tail) vv[12] = xg4[1536 + tid];

    // W -> SMEM: interleaved column-pair layout, masked columns zeroed
    for (int j = wid; j < 26; j += 4) {
        int c0 = 2 * j, c1 = 2 * j + 1;
        ull w0 = sm_sh[c0] ? 0ull : *(const ull*)(W + c0 * DD + 2 * lane);
        ull w1 = (c1 < CC && !sm_sh[c1]) ? *(const ull*)(W + c1 * DD + 2 * lane) : 0ull;
        ulonglong2 t; t.x = w0; t.y = w1;
        Wsh2[j * 32 + lane] = t;
    }
    __syncthreads();                                         // #2 (slotmap ready)

    // ---- phase 3: scatter x into compacted duplicated rows ----
#pragma unroll
    for (int k = 0; k < 13; ++k) {
        if (k < 12 || tail) {
            float4 v = vv[k];
            int idx = 4 * tid + 512 * k;
            int t = idx / CC;
            int c = idx - t * CC;
            int s = slotmap[t];
            if (s >= 0) xs[s * 52 + c] = dup2(v.x);
            if (++c == CC) { c = 0; s = slotmap[++t]; }
            if (s >= 0) xs[s * 52 + c] = dup2(v.y);
            if (++c == CC) { c = 0; s = slotmap[++t]; }
            if (s >= 0) xs[s * 52 + c] = dup2(v.z);
            if (++c == CC) { c = 0; s = slotmap[++t]; }
            if (s >= 0) xs[s * 52 + c] = dup2(v.w);
        }
    }

    // ---- per-lane constants + masked-token constant stores ----
    const float2 bb   = *(const float2*)(g_bias + b * DD + 2 * lane);
    const ull    bll  = pack2(bb.x, bb.y);
    const float2 cvec = g_cvec[b * 32 + lane];
    const float2 g2   = *(const float2*)(gamma + 2 * lane);
    const float2 b2   = *(const float2*)(beta  + 2 * lane);
    float2* out2 = (float2*)out;
    {
        unsigned mm = ~um;
        float2* ob = out2 + (tok0 + wid * 32) * 32 + lane;
#pragma unroll
        for (int r = 0; r < 32; ++r)
            if ((mm >> r) & 1u) ob[r * 32] = cvec;
    }
    __syncthreads();                                         // #3 (xs + Wsh2 ready)

    // ---- phase 4: compute — contiguous groups of 16 slots, 16 FFMA2 chains ----
    for (int g = wid; g < ngroups; g += 4) {
        const int base = g * 16;
        const int nv   = nslots - base;                      // >=1; >=16 except last

        const ulonglong2* xb = (const ulonglong2*)(xs + base * 52);
        ull acc[16];
#pragma unroll
        for (int k = 0; k < 16; ++k) acc[k] = bll;

#pragma unroll
        for (int gi = 0; gi < 13; ++gi) {
            ulonglong2 wA = Wsh2[(2 * gi) * 32 + lane];      // cols 4gi, 4gi+1
            ulonglong2 wB = Wsh2[(2 * gi + 1) * 32 + lane];  // cols 4gi+2, 4gi+3
#pragma unroll
            for (int k = 0; k < 16; ++k) {
                ulonglong2 u = xb[k * 26 + 2 * gi];
                ulonglong2 v = xb[k * 26 + 2 * gi + 1];
                FMA2(acc[k], u.x, wA.x, acc[k]);
                FMA2(acc[k], u.y, wA.y, acc[k]);
                FMA2(acc[k], v.x, wB.x, acc[k]);
                FMA2(acc[k], v.y, wB.y, acc[k]);
            }
        }

        // ---- LN in two batches of 8 chains (caps register pressure) ----
#pragma unroll
        for (int h = 0; h < 2; ++h) {
            float xv[8], yv[8], sv[8], qv[8];
#pragma unroll
            for (int k = 0; k < 8; ++k) {
                ull a = acc[h * 8 + k];
                xv[k] = lo32(a); yv[k] = hi32(a);
                sv[k] = xv[k] + yv[k];
                qv[k] = xv[k] * xv[k] + yv[k] * yv[k];
            }
#pragma unroll
            for (int o = 16; o > 0; o >>= 1) {
#pragma unroll
                for (int k = 0; k < 8; ++k) {
                    sv[k] += __shfl_xor_sync(0xffffffffu, sv[k], o);
                    qv[k] += __shfl_xor_sync(0xffffffffu, qv[k], o);
                }
            }
#pragma unroll
            for (int k = 0; k < 8; ++k) {
                int kk = h * 8 + k;
                float mu = sv[k] * (1.f / 64.f);
                float r  = rsqrtf(fmaf(-mu, mu, qv[k] * (1.f / 64.f)) + LN_EPS);
                if (kk < nv) {
                    float2 o2;
                    o2.x = fmaf((xv[k] - mu) * r, g2.x, b2.x);
                    o2.y = fmaf((yv[k] - mu) * r, g2.y, b2.y);
                    out2[(tok0 + tokmap[base + kk]) * 32 + lane] = o2;
                }
            }
        }
    }
}

extern "C" void kernel_launch(void* const* d_in, const int* in_sizes, int n_in,
                              void* d_out, int out_size)
{
    const float* x     = (const float*)d_in[0];
    const float* W     = (const float*)d_in[1];
    const float* Wm    = (const float*)d_in[2];
    const float* gamma = (const float*)d_in[3];
    const float* beta  = (const float*)d_in[4];
    const void*  tmask = d_in[5];
    const void*  smask = d_in[6];

    (void)in_sizes; (void)n_in; (void)out_size;

    cudaFuncSetAttribute(fused_proj_ln_kernel,
                         cudaFuncAttributeMaxDynamicSharedMemorySize, SM_TOTAL);

    precompute_batch_kernel<<<BB, 32>>>(Wm, smask, gamma, beta,
                                        (const unsigned*)tmask);

    const int nblocks = BB * (TT / 128);   // 2048
    fused_proj_ln_kernel<<<nblocks, NTHREADS, SM_TOTAL>>>(
        x, W, gamma, beta, tmask, smask, (float*)d_out);
}

// round 13
// speedup vs baseline: 2.3233x; 1.7491x over previous
#include <cuda_runtime.h>
#include <cstdint>

#define BB 64
#define TT 4096
#define CC 51
#define DD 64
#define NTHREADS 128
#define LN_EPS 1e-5f

typedef unsigned long long ull;

// Packed fp32x2 FMA (Blackwell FFMA2 — PTX-only)
#define FMA2(d, a, b, c) \
    asm("fma.rn.f32x2 %0, %1, %2, %3;" : "=l"(d) : "l"(a), "l"(b), "l"(c))
// Build (f,f) register pair from one float (single MOV pair, ALU pipe)
#define DUPF(d, f) \
    asm("mov.b64 %0, {%1, %1};" : "=l"(d) : "f"(f))

static __device__ __forceinline__ float lo32(ull v) { return __uint_as_float((unsigned)v); }
static __device__ __forceinline__ float hi32(ull v) { return __uint_as_float((unsigned)(v >> 32)); }
static __device__ __forceinline__ ull pack2(float x, float y) {
    return (ull)__float_as_uint(x) | ((ull)__float_as_uint(y) << 32);
}

static __device__ __forceinline__ int mask_val(const void* p, long i, int dt)
{
    if (dt == 1) return ((const int*)p)[i] != 0;
    if (dt == 2) return ((const float*)p)[i] != 0.0f;
    return ((const unsigned char*)p)[i] != 0;
}

// ---------------------------------------------------------------------------
// SMEM layout (bytes):
//   [0)      float xs[128][52]        un-duplicated x, 16B-aligned rows = 26624
//   [26624)  ulonglong2 Wsh2[26][32]  W col-pairs per-lane d            = 13312
//   [39936)  uchar sm_sh[64]
// ---------------------------------------------------------------------------
#define SM_XS    0
#define SM_WD    26624
#define SM_SMSH  39936
#define SM_TOTAL 40000

extern "C" __global__ void __launch_bounds__(NTHREADS, 3)
fused_proj_ln_kernel(const float* __restrict__ x,
                     const float* __restrict__ W,
                     const float* __restrict__ Wm,
                     const float* __restrict__ gamma,
                     const float* __restrict__ beta,
                     const void* __restrict__ time_mask,
                     const void* __restrict__ sensor_mask,
                     float* __restrict__ out)
{
    extern __shared__ char smem[];
    float*         xs    = (float*)(smem + SM_XS);        // [128][52]
    ulonglong2*    Wsh2  = (ulonglong2*)(smem + SM_WD);   // [26][32]
    unsigned char* sm_sh = (unsigned char*)(smem + SM_SMSH);

    const int tid  = threadIdx.x;
    const int lane = tid & 31;
    const int wid  = tid >> 5;

    const int  b    = blockIdx.x >> 5;            // 32 tiles per batch
    const int  tb   = (blockIdx.x & 31) * 128;
    const long tok0 = (long)b * TT + tb;

    // ---- phase 0: start x LDG batch (MLP-13) + detect-word load ----
    const float4* xg4 = (const float4*)(x + tok0 * CC);   // 1632 float4 / tile
    float4 vv[13];
#pragma unroll
    for (int k = 0; k < 12; ++k) vv[k] = xg4[tid + 128 * k];
    const bool tail = tid < 96;
    if (tail) vv[12] = xg4[1536 + tid];

    // in-block mask-dtype detection from the first 128 words of time_mask
    // (valid for every candidate dtype; classification unambiguous w.h.p.)
    const unsigned dw = ((const unsigned*)time_mask)[tid];
    const int dtI = __syncthreads_and(dw <= 1u);
    const int dtF = __syncthreads_and(dw == 0u || dw == 0x3f800000u);
    const int dt  = dtI ? 1 : (dtF ? 2 : 0);

    // ---- phase 1: masks, pad column ----
    if (tid < CC) sm_sh[tid] = (unsigned char)mask_val(sensor_mask, (long)b * CC + tid, dt);
    xs[tid * 52 + 51] = 0.0f;                     // pad col c=51

    const int un = !mask_val(time_mask, tok0 + tid, dt);  // warp wid owns tokens wid*32..+31
    const unsigned um = __ballot_sync(0xffffffffu, un);
    __syncthreads();                              // sm_sh ready

    // ---- phase 2: W -> SMEM (masked cols zeroed), x scatter, bias/cvec ----
    for (int j = wid; j < 26; j += 4) {
        int c0 = 2 * j, c1 = 2 * j + 1;
        ull w0 = sm_sh[c0] ? 0ull : *(const ull*)(W + c0 * DD + 2 * lane);
        ull w1 = (c1 < CC && !sm_sh[c1]) ? *(const ull*)(W + c1 * DD + 2 * lane) : 0ull;
        ulonglong2 t; t.x = w0; t.y = w1;
        Wsh2[j * 32 + lane] = t;
    }

    // scatter x (all tokens; no indirection): 4 scalar STS per float4
#pragma unroll
    for (int k = 0; k < 13; ++k) {
        if (k < 12 || tail) {
            float4 v = vv[k];
            int idx = 4 * tid + 512 * k;
            int t = idx / CC;
            int c = idx - t * CC;
            xs[t * 52 + c] = v.x;
            if (++c == CC) { c = 0; ++t; }
            xs[t * 52 + c] = v.y;
            if (++c == CC) { c = 0; ++t; }
            xs[t * 52 + c] = v.z;
            if (++c == CC) { c = 0; ++t; }
            xs[t * 52 + c] = v.w;
        }
    }

    // per-batch bias (sum Wm over masked c) + global Wm sum (dual accumulators)
    float2 wsA = make_float2(0.f, 0.f), wsB = make_float2(0.f, 0.f);
    float2 bsA = make_float2(0.f, 0.f), bsB = make_float2(0.f, 0.f);
#pragma unroll
    for (int c = 0; c < CC; ++c) {
        float2 wm = *(const float2*)(Wm + c * DD + 2 * lane);
        if (c & 1) { wsB.x += wm.x; wsB.y += wm.y; if (sm_sh[c]) { bsB.x += wm.x; bsB.y += wm.y; } }
        else       { wsA.x += wm.x; wsA.y += wm.y; if (sm_sh[c]) { bsA.x += wm.x; bsA.y += wm.y; } }
    }
    const float2 wsum = make_float2(wsA.x + wsB.x, wsA.y + wsB.y);
    const ull    bll  = pack2(bsA.x + bsB.x, bsA.y + bsB.y);

    const float2 g2 = *(const float2*)(gamma + 2 * lane);
    const float2 b2 = *(const float2*)(beta  + 2 * lane);

    // constant row for time-masked tokens: LN(sum_all_c Wm)
    float2 cvec;
    {
        float s = wsum.x + wsum.y;
        float q = wsum.x * wsum.x + wsum.y * wsum.y;
#pragma unroll
        for (int o = 16; o > 0; o >>= 1) {
            s += __shfl_xor_sync(0xffffffffu, s, o);
            q += __shfl_xor_sync(0xffffffffu, q, o);
        }
        float mu = s * (1.0f / 64.0f);
        float r  = rsqrtf(fmaf(-mu, mu, q * (1.0f / 64.0f)) + LN_EPS);
        cvec.x = fmaf((wsum.x - mu) * r, g2.x, b2.x);
        cvec.y = fmaf((wsum.y - mu) * r, g2.y, b2.y);
    }

    // time-masked tokens: predicated constant-row stores (global; no sync needed)
    float2* out2 = (float2*)out;
    const int  rbase = wid * 32;
    const long otok  = tok0 + rbase;
    {
        unsigned mm = ~um;
        float2* ob = out2 + otok * 32 + lane;
#pragma unroll
        for (int r = 0; r < 32; ++r)
            if ((mm >> r) & 1u) ob[r * 32] = cvec;
    }
    __syncthreads();                              // xs + Wsh2 ready

    // ---- phase 3: mainloop — warp-compacted groups of 8 FFMA2 chains ----
    unsigned umw = um;
    while (umw) {
        int r0 = __ffs(umw) - 1; umw &= umw - 1;
        int r1 = r0, r2 = r0, r3 = r0, r4 = r0, r5 = r0, r6 = r0, r7 = r0;
        int nv = 1;
        if (umw) { r1 = __ffs(umw) - 1; umw &= umw - 1; nv = 2; }
        if (umw) { r2 = __ffs(umw) - 1; umw &= umw - 1; nv = 3; }
        if (umw) { r3 = __ffs(umw) - 1; umw &= umw - 1; nv = 4; }
        if (umw) { r4 = __ffs(umw) - 1; umw &= umw - 1; nv = 5; }
        if (umw) { r5 = __ffs(umw) - 1; umw &= umw - 1; nv = 6; }
        if (umw) { r6 = __ffs(umw) - 1; umw &= umw - 1; nv = 7; }
        if (umw) { r7 = __ffs(umw) - 1; umw &= umw - 1; nv = 8; }

        const float* p0 = xs + (rbase + r0) * 52;
        const float* p1 = xs + (rbase + r1) * 52;
        const float* p2 = xs + (rbase + r2) * 52;
        const float* p3 = xs + (rbase + r3) * 52;
        const float* p4 = xs + (rbase + r4) * 52;
        const float* p5 = xs + (rbase + r5) * 52;
        const float* p6 = xs + (rbase + r6) * 52;
        const float* p7 = xs + (rbase + r7) * 52;

        ull a0 = bll, a1 = bll, a2 = bll, a3 = bll;
        ull a4 = bll, a5 = bll, a6 = bll, a7 = bll;
        ull d0, d1, d2, d3, d4, d5, d6, d7;

#pragma unroll
        for (int gi = 0; gi < 13; ++gi) {
            ulonglong2 wA = Wsh2[(2 * gi) * 32 + lane];      // cols 4gi, 4gi+1
            ulonglong2 wB = Wsh2[(2 * gi + 1) * 32 + lane];  // cols 4gi+2, 4gi+3
            float4 u0 = *(const float4*)(p0 + 4 * gi);       // broadcast LDS.128
            float4 u1 = *(const float4*)(p1 + 4 * gi);
            float4 u2 = *(const float4*)(p2 + 4 * gi);
            float4 u3 = *(const float4*)(p3 + 4 * gi);
            float4 u4 = *(const float4*)(p4 + 4 * gi);
            float4 u5 = *(const float4*)(p5 + 4 * gi);
            float4 u6 = *(const float4*)(p6 + 4 * gi);
            float4 u7 = *(const float4*)(p7 + 4 * gi);

            DUPF(d0, u0.x); FMA2(a0, d0, wA.x, a0);
            DUPF(d1, u1.x); FMA2(a1, d1, wA.x, a1);
            DUPF(d2, u2.x); FMA2(a2, d2, wA.x, a2);
            DUPF(d3, u3.x); FMA2(a3, d3, wA.x, a3);
            DUPF(d4, u4.x); FMA2(a4, d4, wA.x, a4);
            DUPF(d5, u5.x); FMA2(a5, d5, wA.x, a5);
            DUPF(d6, u6.x); FMA2(a6, d6, wA.x, a6);
            DUPF(d7, u7.x); FMA2(a7, d7, wA.x, a7);

            DUPF(d0, u0.y); FMA2(a0, d0, wA.y, a0);
            DUPF(d1, u1.y); FMA2(a1, d1, wA.y, a1);
            DUPF(d2, u2.y); FMA2(a2, d2, wA.y, a2);
            DUPF(d3, u3.y); FMA2(a3, d3, wA.y, a3);
            DUPF(d4, u4.y); FMA2(a4, d4, wA.y, a4);
            DUPF(d5, u5.y); FMA2(a5, d5, wA.y, a5);
            DUPF(d6, u6.y); FMA2(a6, d6, wA.y, a6);
            DUPF(d7, u7.y); FMA2(a7, d7, wA.y, a7);

            DUPF(d0, u0.z); FMA2(a0, d0, wB.x, a0);
            DUPF(d1, u1.z); FMA2(a1, d1, wB.x, a1);
            DUPF(d2, u2.z); FMA2(a2, d2, wB.x, a2);
            DUPF(d3, u3.z); FMA2(a3, d3, wB.x, a3);
            DUPF(d4, u4.z); FMA2(a4, d4, wB.x, a4);
            DUPF(d5, u5.z); FMA2(a5, d5, wB.x, a5);
            DUPF(d6, u6.z); FMA2(a6, d6, wB.x, a6);
            DUPF(d7, u7.z); FMA2(a7, d7, wB.x, a7);

            DUPF(d0, u0.w); FMA2(a0, d0, wB.y, a0);
            DUPF(d1, u1.w); FMA2(a1, d1, wB.y, a1);
            DUPF(d2, u2.w); FMA2(a2, d2, wB.y, a2);
            DUPF(d3, u3.w); FMA2(a3, d3, wB.y, a3);
            DUPF(d4, u4.w); FMA2(a4, d4, wB.y, a4);
            DUPF(d5, u5.w); FMA2(a5, d5, wB.y, a5);
            DUPF(d6, u6.w); FMA2(a6, d6, wB.y, a6);
            DUPF(d7, u7.w); FMA2(a7, d7, wB.y, a7);
        }

        // ---- fused LN for 8 chains + guarded stores ----
        ull aa[8] = {a0, a1, a2, a3, a4, a5, a6, a7};
        int rr[8] = {r0, r1, r2, r3, r4, r5, r6, r7};
        float xv[8], yv[8], sv[8], qv[8];
#pragma unroll
        for (int k = 0; k < 8; ++k) {
            xv[k] = lo32(aa[k]); yv[k] = hi32(aa[k]);
            sv[k] = xv[k] + yv[k];
            qv[k] = xv[k] * xv[k] + yv[k] * yv[k];
        }
#pragma unroll
        for (int o = 16; o > 0; o >>= 1) {
#pragma unroll
            for (int k = 0; k < 8; ++k) {
                sv[k] += __shfl_xor_sync(0xffffffffu, sv[k], o);
                qv[k] += __shfl_xor_sync(0xffffffffu, qv[k], o);
            }
        }
#pragma unroll
        for (int k = 0; k < 8; ++k) {
            float mu = sv[k] * (1.f / 64.f);
            float r  = rsqrtf(fmaf(-mu, mu, qv[k] * (1.f / 64.f)) + LN_EPS);
            if (k < nv) {
                float2 o2;
                o2.x = fmaf((xv[k] - mu) * r, g2.x, b2.x);
                o2.y = fmaf((yv[k] - mu) * r, g2.y, b2.y);
                out2[(otok + rr[k]) * 32 + lane] = o2;
            }
        }
    }
}

extern "C" void kernel_launch(void* const* d_in, const int* in_sizes, int n_in,
                              void* d_out, int out_size)
{
    const float* x     = (const float*)d_in[0];
    const float* W     = (const float*)d_in[1];
    const float* Wm    = (const float*)d_in[2];
    const float* gamma = (const float*)d_in[3];
    const float* beta  = (const float*)d_in[4];
    const void*  tmask = d_in[5];
    const void*  smask = d_in[6];

    (void)in_sizes; (void)n_in; (void)out_size;

    cudaFuncSetAttribute(fused_proj_ln_kernel,
                         cudaFuncAttributeMaxDynamicSharedMemorySize, SM_TOTAL);

    const int nblocks = BB * (TT / 128);   // 2048; single launch, no aux kernels
    fused_proj_ln_kernel<<<nblocks, NTHREADS, SM_TOTAL>>>(
        x, W, Wm, gamma, beta, tmask, smask, (float*)d_out);
}